// round 1
// baseline (speedup 1.0000x reference)
#include <cuda_runtime.h>
#include <cuda_bf16.h>
#include <cstdint>

// Problem constants (from reference): VOCAB=4, D=128, R<=2000 segments.
#define VOCAB 4
#define DIM   128
#define MAX_SEGS 8192          // generous headroom over R=2000
#define CHUNK 32               // contiguous tokens per thread (run-length aggregation)

// Per-segment, per-vocab token histogram. Zero-initialized at module load;
// the combine kernel re-zeros its slots after consuming them, so the
// "all-zero on entry" invariant holds for every kernel_launch call
// (correctness run and each graph replay alike).
__device__ int g_counts[MAX_SEGS * VOCAB];

// ---------------------------------------------------------------------------
// Kernel 1: per-thread run-length histogram over sorted segment_ids.
// Each thread owns a contiguous CHUNK of tokens. Counts for the current
// segment are packed 4x16-bit into one uint64 (CHUNK=32 < 65536, no overflow),
// flushed with global atomicAdd (compiles to RED, fire-and-forget) only when
// the segment id changes -> ~4 atomics per thread instead of 1 per token.
// ---------------------------------------------------------------------------
__device__ __forceinline__ void flush_counts(int seg, unsigned long long cnt) {
    if (cnt == 0ull) return;
    #pragma unroll
    for (int v = 0; v < VOCAB; v++) {
        unsigned c = (unsigned)((cnt >> (16 * v)) & 0xFFFFull);
        if (c) atomicAdd(&g_counts[seg * VOCAB + v], (int)c);
    }
}

__global__ void hist_kernel(const int* __restrict__ tokens,
                            const int* __restrict__ segids,
                            int T) {
    long long base = (long long)(blockIdx.x * blockDim.x + threadIdx.x) * CHUNK;
    if (base >= T) return;
    int end = (int)min((long long)T, base + CHUNK);
    int i   = (int)base;

    int cur = __ldg(&segids[i]);
    unsigned long long cnt = 0ull;

    if (end - i == CHUNK) {
        // base is CHUNK-aligned -> 16B-aligned; vector path.
        const int4* t4 = (const int4*)(tokens + i);
        const int4* s4 = (const int4*)(segids + i);
        #pragma unroll
        for (int k = 0; k < CHUNK / 4; k++) {
            int4 tk = __ldg(&t4[k]);
            int4 sg = __ldg(&s4[k]);
            int tt[4] = {tk.x, tk.y, tk.z, tk.w};
            int ss[4] = {sg.x, sg.y, sg.z, sg.w};
            #pragma unroll
            for (int j = 0; j < 4; j++) {
                if (ss[j] != cur) { flush_counts(cur, cnt); cnt = 0ull; cur = ss[j]; }
                cnt += 1ull << (tt[j] << 4);
            }
        }
    } else {
        for (; i < end; i++) {
            int s = __ldg(&segids[i]);
            int t = __ldg(&tokens[i]);
            if (s != cur) { flush_counts(cur, cnt); cnt = 0ull; cur = s; }
            cnt += 1ull << (t << 4);
        }
    }
    flush_counts(cur, cnt);
}

// ---------------------------------------------------------------------------
// Kernel 2: out[r][d] = (sum_v cnt[r][v] * emb[v][d]) / max(sum_v cnt[r][v], 1)
// One block per segment, one thread per dim. After reading, re-zero the
// counters for the next launch (sync first so every thread has read them).
// ---------------------------------------------------------------------------
__global__ void combine_kernel(const float* __restrict__ emb,
                               float* __restrict__ out) {
    int r = blockIdx.x;
    int d = threadIdx.x;

    int c0 = g_counts[r * VOCAB + 0];
    int c1 = g_counts[r * VOCAB + 1];
    int c2 = g_counts[r * VOCAB + 2];
    int c3 = g_counts[r * VOCAB + 3];

    float tot = (float)(c0 + c1 + c2 + c3);
    float inv = 1.0f / fmaxf(tot, 1.0f);

    float acc = (float)c0 * __ldg(&emb[0 * DIM + d])
              + (float)c1 * __ldg(&emb[1 * DIM + d])
              + (float)c2 * __ldg(&emb[2 * DIM + d])
              + (float)c3 * __ldg(&emb[3 * DIM + d]);

    out[r * DIM + d] = acc * inv;

    __syncthreads();                 // all reads of g_counts done
    if (d < VOCAB) g_counts[r * VOCAB + d] = 0;   // restore invariant
}

// ---------------------------------------------------------------------------
// Launch. Inputs (metadata order): tokens[T] i32, segment_ids[T] i32,
// embedding[VOCAB*DIM] f32, n_reads (scalar). R derived from out_size.
// ---------------------------------------------------------------------------
extern "C" void kernel_launch(void* const* d_in, const int* in_sizes, int n_in,
                              void* d_out, int out_size) {
    const int* tokens = (const int*)d_in[0];
    const int* segids = (const int*)d_in[1];
    const float* emb  = (const float*)d_in[2];
    float* out        = (float*)d_out;

    int T = in_sizes[0];
    int R = out_size / DIM;

    int threads_total = (T + CHUNK - 1) / CHUNK;
    int block = 256;
    int grid  = (threads_total + block - 1) / block;

    hist_kernel<<<grid, block>>>(tokens, segids, T);
    combine_kernel<<<R, DIM>>>(emb, out);
}

// round 2
// speedup vs baseline: 1.1358x; 1.1358x over previous
#include <cuda_runtime.h>
#include <cuda_bf16.h>
#include <cstdint>

#define VOCAB 4
#define DIM   128
#define MAX_SEGS 8192
#define CHUNK 32              // tokens per thread; base is 128B-aligned

// Per-segment, per-vocab histogram. Zeroed at load; combine_kernel re-zeros
// after consuming -> invariant "all zero on entry" holds every launch/replay.
__device__ int g_counts[MAX_SEGS * VOCAB];

// Recover n0..n3 from (n, ssum=Σt, s0=Σ(t&1), s3=Σ(t==3)) and flush.
//   n3 = s3 ; n1 = s0 - s3 ; n2 = (ssum - s0 - 2*s3)/2 ; n0 = n - n1 - n2 - n3
__device__ __forceinline__ void flush_counts(int seg, int n, int ssum, int s0, int s3) {
    if (n == 0) return;
    int n3 = s3;
    int n1 = s0 - s3;
    int n2 = (ssum - s0 - 2 * s3) >> 1;
    int n0 = n - n1 - n2 - n3;
    int* base = &g_counts[seg * VOCAB];
    if (n0) atomicAdd(base + 0, n0);
    if (n1) atomicAdd(base + 1, n1);
    if (n2) atomicAdd(base + 2, n2);
    if (n3) atomicAdd(base + 3, n3);
}

__global__ void hist_kernel(const int* __restrict__ tokens,
                            const int* __restrict__ segids,
                            int T) {
    long long base_ll = (long long)(blockIdx.x * blockDim.x + threadIdx.x) * CHUNK;
    if (base_ll >= T) return;
    int base = (int)base_ll;

    if (base + CHUNK <= T) {
        int s_first = __ldg(&segids[base]);
        int s_last  = __ldg(&segids[base + CHUNK - 1]);
        if (s_first == s_last) {
            // ---- fast path: whole chunk in one segment, branch-free count ----
            const int4* t4 = (const int4*)(tokens + base);
            int ssum = 0, s0 = 0, s3 = 0;
            #pragma unroll
            for (int k = 0; k < CHUNK / 4; k++) {
                int4 tk = __ldg(&t4[k]);
                // pack low bytes of 4 token words: p = [x0,y0,z0,w0]
                unsigned a = __byte_perm((unsigned)tk.x, (unsigned)tk.y, 0x0040);
                unsigned b = __byte_perm((unsigned)tk.z, (unsigned)tk.w, 0x0040);
                unsigned p = __byte_perm(a, b, 0x5410);
                unsigned u  = p >> 1;
                unsigned b0 = p & 0x01010101u;          // bit0 per token
                unsigned b3 = p & u & 0x01010101u;      // 1 iff token==3
                ssum = __dp4a((int)p,  0x01010101, ssum);   // Σ t
                s0   = __dp4a((int)b0, 0x01010101, s0);     // Σ (t&1)
                s3   = __dp4a((int)b3, 0x01010101, s3);     // Σ (t==3)
            }
            flush_counts(s_first, CHUNK, ssum, s0, s3);
            return;
        }
    }

    // ---- slow path: chunk crosses a segment boundary (or tail) ----
    int end = (int)min((long long)T, base_ll + CHUNK);
    int cur = __ldg(&segids[base]);
    int n = 0, ssum = 0, s0 = 0, s3 = 0;
    for (int i = base; i < end; i++) {
        int s = __ldg(&segids[i]);
        int t = __ldg(&tokens[i]);
        if (s != cur) {
            flush_counts(cur, n, ssum, s0, s3);
            n = 0; ssum = 0; s0 = 0; s3 = 0; cur = s;
        }
        n++;
        ssum += t;
        s0   += t & 1;
        s3   += (t == 3);
    }
    flush_counts(cur, n, ssum, s0, s3);
}

// ---------------------------------------------------------------------------
// Combine: one warp per segment, one float4 per lane (32 lanes x 4 = 128 dims).
// out[r][:] = (Σ_v cnt[r][v] * emb[v][:]) / max(Σ_v cnt[r][v], 1)
// Lane 0 re-zeros the segment's counters afterward (restores invariant).
// ---------------------------------------------------------------------------
__global__ void combine_kernel(const float* __restrict__ emb,
                               float* __restrict__ out, int R) {
    int tid  = blockIdx.x * blockDim.x + threadIdx.x;
    int seg  = tid >> 5;
    int lane = tid & 31;
    if (seg >= R) return;

    int4 c = *(const int4*)&g_counts[seg * VOCAB];
    float f0 = (float)c.x, f1 = (float)c.y, f2 = (float)c.z, f3 = (float)c.w;
    float inv = 1.0f / fmaxf(f0 + f1 + f2 + f3, 1.0f);

    const float4* e = (const float4*)emb;   // row v: float4 index v*32 + lane
    float4 e0 = __ldg(&e[0 * 32 + lane]);
    float4 e1 = __ldg(&e[1 * 32 + lane]);
    float4 e2 = __ldg(&e[2 * 32 + lane]);
    float4 e3 = __ldg(&e[3 * 32 + lane]);

    float4 r;
    r.x = (f0 * e0.x + f1 * e1.x + f2 * e2.x + f3 * e3.x) * inv;
    r.y = (f0 * e0.y + f1 * e1.y + f2 * e2.y + f3 * e3.y) * inv;
    r.z = (f0 * e0.z + f1 * e1.z + f2 * e2.z + f3 * e3.z) * inv;
    r.w = (f0 * e0.w + f1 * e1.w + f2 * e2.w + f3 * e3.w) * inv;

    ((float4*)out)[seg * 32 + lane] = r;

    __syncwarp();
    if (lane == 0)
        *(int4*)&g_counts[seg * VOCAB] = make_int4(0, 0, 0, 0);
}

extern "C" void kernel_launch(void* const* d_in, const int* in_sizes, int n_in,
                              void* d_out, int out_size) {
    const int* tokens = (const int*)d_in[0];
    const int* segids = (const int*)d_in[1];
    const float* emb  = (const float*)d_in[2];
    float* out        = (float*)d_out;

    int T = in_sizes[0];
    int R = out_size / DIM;

    int threads_total = (T + CHUNK - 1) / CHUNK;
    int block = 256;
    int grid  = (threads_total + block - 1) / block;
    hist_kernel<<<grid, block>>>(tokens, segids, T);

    int cthreads = R * 32;
    int cgrid = (cthreads + 255) / 256;
    combine_kernel<<<cgrid, 256>>>(emb, out, R);
}